// round 13
// baseline (speedup 1.0000x reference)
#include <cuda_runtime.h>

#define Nn 50000
#define INd 128
#define Hh 4
#define Ff 32
#define Ee 500000
#define Ll 512
#define SLOPE 0.2f
#define NCHUNK 2
#define CHUNK ((Nn + NCHUNK - 1) / NCHUNK)   // 25000 src nodes -> 51.2 MB of y per chunk

// ---------------- device scratch (static, allocation-free) ----------------
__device__ __align__(16) float  g_fs[Nn * INd];       // feat_src (N,128)
__device__ __align__(16) float  g_fd[Nn * INd];       // feat_dst (N,128)
__device__ __align__(16) float4 g_ex[2][Ee];          // per-edge exp(logit) by head, CSR slots
__device__ __align__(16) float4 g_rs[2][Nn];          // per-node 1/denominator by head
__device__ __align__(16) float4 g_yh[Nn * (Ll / 4)];  // label partial between chunk launches
__device__               int    g_cnt[2][Nn];         // in-degree histogram
__device__               int    g_off[2][Nn];         // CSR slot base (block-aggregated alloc)
__device__               int    g_cur[2][Nn];         // fill cursors
__device__               int    g_srcs[2][Ee];        // src ids, grouped by dst
__device__               int    g_total[2];           // slot allocator
__device__               int    g_flag_fmt;           // 0=int32, 1=uint8, 2=float32

// ---------------- init: flag detect (block 0) + zero histograms/totals ----------------
__global__ void k_init(const unsigned* __restrict__ p) {
    if (blockIdx.x == 0) {
        __shared__ int s_word_not01, s_byte_not01;
        if (threadIdx.x == 0) { s_word_not01 = 0; s_byte_not01 = 0; g_total[0] = 0; g_total[1] = 0; }
        __syncthreads();
        const int nwords = Nn / 4;
        int w_bad = 0, b_bad = 0;
        for (int i = threadIdx.x; i < nwords; i += blockDim.x) {
            unsigned w = p[i];
            if (w > 1u) w_bad = 1;
            unsigned b0 = w & 0xFFu, b1 = (w >> 8) & 0xFFu, b2 = (w >> 16) & 0xFFu, b3 = (w >> 24) & 0xFFu;
            if (b0 > 1u || b1 > 1u || b2 > 1u || b3 > 1u) b_bad = 1;
        }
        if (w_bad) atomicOr(&s_word_not01, 1);
        if (b_bad) atomicOr(&s_byte_not01, 1);
        __syncthreads();
        if (threadIdx.x == 0) {
            int fmt;
            if (!s_word_not01) fmt = 0;
            else if (!s_byte_not01) fmt = 1;
            else fmt = 2;
            g_flag_fmt = fmt;
        }
    } else {
        int tid = (blockIdx.x - 1) * blockDim.x + threadIdx.x;
        int stride = (gridDim.x - 1) * blockDim.x;
        int* cnt = (int*)g_cnt;
        for (int i = tid; i < 2 * Nn; i += stride) cnt[i] = 0;
    }
}

// ---------------- projection: fs = x W_src^T + b_src ; fd likewise ----------------
#define BR 16
__global__ void k_proj(const float* __restrict__ x,
                       const float* __restrict__ Ws, const float* __restrict__ bs,
                       const float* __restrict__ Wd, const float* __restrict__ bd) {
    __shared__ float xs[BR][INd];
    const int row0 = blockIdx.x * BR;
    for (int i = threadIdx.x; i < BR * INd; i += blockDim.x) {
        int r = i / INd, c = i % INd;
        xs[r][c] = x[(row0 + r) * INd + c];
    }
    __syncthreads();
    const int col = threadIdx.x;
    float accS[BR], accD[BR];
#pragma unroll
    for (int r = 0; r < BR; r++) { accS[r] = 0.f; accD[r] = 0.f; }
    const float* wsr = Ws + col * INd;
    const float* wdr = Wd + col * INd;
    for (int k = 0; k < INd; k++) {
        float ws = __ldg(wsr + k);
        float wd = __ldg(wdr + k);
#pragma unroll
        for (int r = 0; r < BR; r++) {
            float xv = xs[r][k];
            accS[r] += xv * ws;
            accD[r] += xv * wd;
        }
    }
    float bsv = bs[col], bdv = bd[col];
#pragma unroll
    for (int r = 0; r < BR; r++) {
        g_fs[(row0 + r) * INd + col] = accS[r] + bsv;
        g_fd[(row0 + r) * INd + col] = accD[r] + bdv;
    }
}

// ---------------- CSR build: histogram -> block-aggregated alloc -> fill ----------------
__global__ void k_hist(const int* __restrict__ dst_p, const int* __restrict__ dst_s, int et) {
    const int g = blockIdx.x >= et;
    const int e = (blockIdx.x - g * et) * blockDim.x + threadIdx.x;
    if (e < Ee) atomicAdd(&g_cnt[g][(g ? dst_s : dst_p)[e]], 1);
}

// 256 threads/block, one node each; in-block exclusive scan + ONE atomic per block.
__global__ void k_alloc(int nbg) {
    const int g = blockIdx.x >= nbg;
    const int b = blockIdx.x - g * nbg;
    const int n = b * 256 + threadIdx.x;
    const int lane = threadIdx.x & 31;
    const int w = threadIdx.x >> 5;

    __shared__ int wsum[8];
    __shared__ int s_base;

    const int c = (n < Nn) ? g_cnt[g][n] : 0;
    int v = c;   // inclusive scan within warp
#pragma unroll
    for (int o = 1; o < 32; o <<= 1) {
        int u = __shfl_up_sync(0xFFFFFFFFu, v, o);
        if (lane >= o) v += u;
    }
    if (lane == 31) wsum[w] = v;
    __syncthreads();
    if (threadIdx.x == 0) {
        int run = 0;
#pragma unroll
        for (int i = 0; i < 8; i++) { int t = wsum[i]; wsum[i] = run; run += t; }
        s_base = (run > 0) ? atomicAdd(&g_total[g], run) : 0;
    }
    __syncthreads();
    if (n < Nn) {
        const int excl = (v - c) + wsum[w] + s_base;
        g_off[g][n] = excl;
        g_cur[g][n] = excl;
    }
}

__global__ void k_fill(const int* __restrict__ src_p, const int* __restrict__ dst_p,
                       const int* __restrict__ src_s, const int* __restrict__ dst_s, int et) {
    const int g = blockIdx.x >= et;
    const int e = (blockIdx.x - g * et) * blockDim.x + threadIdx.x;
    if (e >= Ee) return;
    const int d = (g ? dst_s : dst_p)[e];
    const int s = (g ? src_s : src_p)[e];
    int pos = atomicAdd(&g_cur[g][d], 1);
    g_srcs[g][pos] = s;
}

// ---------------- feature phase: softmax + fs aggregation + h epilogue ----------------
// Exports per-edge ex4 and per-node rs4 for the label chunk kernels.
__global__ void __launch_bounds__(256) k_gfeat(
        const float* __restrict__ x, const float* __restrict__ attn,
        float* __restrict__ out) {
    const int warp = threadIdx.x >> 5;
    const int lane = threadIdx.x & 31;
    const int n = blockIdx.x * (blockDim.x >> 5) + warp;
    if (n >= Nn) return;
    (void)warp;

    const float4* __restrict__ fs4p = (const float4*)g_fs;
    const float4 fd4 = __ldg(((const float4*)g_fd) + n * 32 + lane);
    const float4 at  = __ldg(((const float4*)attn) + lane);

    float4 acc = __ldg(((const float4*)x) + n * 32 + lane);
    acc.x *= 2.f; acc.y *= 2.f; acc.z *= 2.f; acc.w *= 2.f;

#pragma unroll
    for (int g = 0; g < 2; g++) {
        const int beg = g_off[g][n];
        const int end = beg + g_cnt[g][n];
        const int* __restrict__ ps = g_srcs[g];
        float4* __restrict__ pex = g_ex[g];

        float4 accp = make_float4(0.f, 0.f, 0.f, 0.f);
        float dsum = 0.f;   // denominator for head (lane>>3)
        for (int k = beg; k < end; k++) {
            const int s = __ldg(ps + k);
            const float4 f = __ldg(fs4p + s * 32 + lane);
            float v, p;
            v = f.x + fd4.x; v = v > 0.f ? v : SLOPE * v; p  = v * at.x;
            v = f.y + fd4.y; v = v > 0.f ? v : SLOPE * v; p += v * at.y;
            v = f.z + fd4.z; v = v > 0.f ? v : SLOPE * v; p += v * at.z;
            v = f.w + fd4.w; v = v > 0.f ? v : SLOPE * v; p += v * at.w;
            p += __shfl_xor_sync(0xFFFFFFFFu, p, 4);
            p += __shfl_xor_sync(0xFFFFFFFFu, p, 2);
            p += __shfl_xor_sync(0xFFFFFFFFu, p, 1);
            const float ex = expf(p);      // this lane's head value (uniform per 8-lane group)
            dsum += ex;
            accp.x += f.x * ex; accp.y += f.y * ex;
            accp.z += f.z * ex; accp.w += f.w * ex;
            const float e0 = __shfl_sync(0xFFFFFFFFu, ex, 0);
            const float e1 = __shfl_sync(0xFFFFFFFFu, ex, 8);
            const float e2 = __shfl_sync(0xFFFFFFFFu, ex, 16);
            const float e3 = __shfl_sync(0xFFFFFFFFu, ex, 24);
            if (lane == 0) pex[k] = make_float4(e0, e1, e2, e3);
        }
        const float d0 = __shfl_sync(0xFFFFFFFFu, dsum, 0);
        const float d1 = __shfl_sync(0xFFFFFFFFu, dsum, 8);
        const float d2 = __shfl_sync(0xFFFFFFFFu, dsum, 16);
        const float d3 = __shfl_sync(0xFFFFFFFFu, dsum, 24);
        float4 rs;
        rs.x = d0 > 0.f ? 1.f / d0 : 0.f;
        rs.y = d1 > 0.f ? 1.f / d1 : 0.f;
        rs.z = d2 > 0.f ? 1.f / d2 : 0.f;
        rs.w = d3 > 0.f ? 1.f / d3 : 0.f;
        if (lane == 0) g_rs[g][n] = rs;
        const float rl = (lane < 8) ? rs.x : (lane < 16) ? rs.y : (lane < 24) ? rs.z : rs.w;
        acc.x += accp.x * rl; acc.y += accp.y * rl;
        acc.z += accp.z * rl; acc.w += accp.w * rl;
    }

    // ---- epilogue h: mean over heads + elu; heads of float f live in lanes {f/4, +8, +16, +24}
#pragma unroll
    for (int o = 8; o <= 16; o <<= 1) {
        acc.x += __shfl_xor_sync(0xFFFFFFFFu, acc.x, o);
        acc.y += __shfl_xor_sync(0xFFFFFFFFu, acc.y, o);
        acc.z += __shfl_xor_sync(0xFFFFFFFFu, acc.z, o);
        acc.w += __shfl_xor_sync(0xFFFFFFFFu, acc.w, o);
    }
    if (lane < 8) {
        float4 r;
        r.x = acc.x * 0.25f; r.y = acc.y * 0.25f; r.z = acc.z * 0.25f; r.w = acc.w * 0.25f;
        r.x = r.x > 0.f ? r.x : expm1f(r.x);
        r.y = r.y > 0.f ? r.y : expm1f(r.y);
        r.z = r.z > 0.f ? r.z : expm1f(r.z);
        r.w = r.w > 0.f ? r.w : expm1f(r.w);
        ((float4*)out)[n * 8 + lane] = r;
    }
}

// ---------------- label phase, one launch per src-chunk: y stays L2-resident ----------------
__global__ void __launch_bounds__(256) k_glabel(
        const float* __restrict__ y, const void* __restrict__ flag,
        float* __restrict__ out, int c0, int c1, int first, int last) {
    const int warp = threadIdx.x >> 5;
    const int lane = threadIdx.x & 31;
    const int n = blockIdx.x * (blockDim.x >> 5) + warp;
    if (n >= Nn) return;

    const float4* __restrict__ y4 = (const float4*)y;

    float4 yh[4];
    if (first) {
#pragma unroll
        for (int i = 0; i < 4; i++) yh[i] = make_float4(0.f, 0.f, 0.f, 0.f);
    } else {
#pragma unroll
        for (int i = 0; i < 4; i++) yh[i] = __ldcs(g_yh + (size_t)n * 128 + i * 32 + lane);
    }

#pragma unroll
    for (int g = 0; g < 2; g++) {
        const int beg = g_off[g][n];
        const int end = beg + g_cnt[g][n];
        const int* __restrict__ ps = g_srcs[g];
        const float4* __restrict__ pex = g_ex[g];
        const float4 rs = __ldg(&g_rs[g][n]);
        for (int k = beg; k < end; k++) {
            const int s = __ldcs(ps + k);
            if (s < c0 || s >= c1) continue;   // warp-uniform branch
            const float4 e4 = __ldcs(pex + k);
            const float am = 0.25f * (e4.x * rs.x + e4.y * rs.y + e4.z * rs.z + e4.w * rs.w);
            const float4* py = y4 + (size_t)s * 128;
#pragma unroll
            for (int i = 0; i < 4; i++) {
                const float4 v = __ldg(py + i * 32 + lane);
                yh[i].x += v.x * am; yh[i].y += v.y * am;
                yh[i].z += v.z * am; yh[i].w += v.w * am;
            }
        }
    }

    if (!last) {   // spill partial, evict-first
#pragma unroll
        for (int i = 0; i < 4; i++) __stcs(g_yh + (size_t)n * 128 + i * 32 + lane, yh[i]);
        return;
    }

    // ---- epilogue y: L2 normalize or passthrough per flag
    float ssq = 0.f;
#pragma unroll
    for (int i = 0; i < 4; i++)
        ssq += yh[i].x * yh[i].x + yh[i].y * yh[i].y + yh[i].z * yh[i].z + yh[i].w * yh[i].w;
#pragma unroll
    for (int o = 16; o; o >>= 1) ssq += __shfl_xor_sync(0xFFFFFFFFu, ssq, o);
    const float inv = 1.f / fmaxf(sqrtf(ssq), 1e-12f);

    bool f;
    const int fmt = g_flag_fmt;
    if (fmt == 0)      f = ((const int*)flag)[n] != 0;
    else if (fmt == 1) f = ((const unsigned char*)flag)[n] != 0;
    else               f = ((const float*)flag)[n] != 0.f;

    float4* po = (float4*)(out + (size_t)Nn * Ff) + (size_t)n * 128;
    if (f) {
        const float4* py = y4 + (size_t)n * 128;
#pragma unroll
        for (int i = 0; i < 4; i++) po[i * 32 + lane] = __ldg(py + i * 32 + lane);
    } else {
#pragma unroll
        for (int i = 0; i < 4; i++) {
            float4 w = yh[i];
            w.x *= inv; w.y *= inv; w.z *= inv; w.w *= inv;
            po[i * 32 + lane] = w;
        }
    }
}

// ---------------- launch ----------------
extern "C" void kernel_launch(void* const* d_in, const int* in_sizes, int n_in,
                              void* d_out, int out_size) {
    const float* x     = (const float*)d_in[0];
    const float* y     = (const float*)d_in[1];
    const float* Ws    = (const float*)d_in[2];
    const float* bs    = (const float*)d_in[3];
    const float* Wd    = (const float*)d_in[4];
    const float* bd    = (const float*)d_in[5];
    const float* attn  = (const float*)d_in[6];
    const int*   src_p = (const int*)d_in[7];
    const int*   dst_p = (const int*)d_in[8];
    const int*   src_s = (const int*)d_in[9];
    const int*   dst_s = (const int*)d_in[10];
    const void*  dflag = d_in[11];
    float* out = (float*)d_out;

    const int et = (Ee + 255) / 256;     // thread-per-edge blocks (per graph)
    const int nbg = (Nn + 255) / 256;    // alloc blocks (per graph)
    const int nw = (Nn + 7) / 8;         // warp-per-node blocks

    k_init<<<129, 256>>>((const unsigned*)dflag);
    k_proj<<<Nn / BR, 128>>>(x, Ws, bs, Wd, bd);

    k_hist<<<2 * et, 256>>>(dst_p, dst_s, et);
    k_alloc<<<2 * nbg, 256>>>(nbg);
    k_fill<<<2 * et, 256>>>(src_p, dst_p, src_s, dst_s, et);

    k_gfeat<<<nw, 256>>>(x, attn, out);
    for (int c = 0; c < NCHUNK; c++) {
        const int c0 = c * CHUNK;
        const int c1 = (c + 1 == NCHUNK) ? Nn : (c + 1) * CHUNK;
        k_glabel<<<nw, 256>>>(y, dflag, out, c0, c1, c == 0, c + 1 == NCHUNK);
    }
}

// round 14
// speedup vs baseline: 1.0523x; 1.0523x over previous
#include <cuda_runtime.h>
#include <cuda_bf16.h>

#define Nn 50000
#define INd 128
#define Hh 4
#define Ff 32
#define Ee 500000
#define Ll 512
#define SLOPE 0.2f
#define MAXD 128   // per-warp smem edge stash; P(deg>=128 | Poisson(10)) ~ 1e-80

// ---------------- device scratch (static, allocation-free) ----------------
__device__ __align__(16) float          g_fs[Nn * INd];   // feat_src (N,128)
__device__ __align__(16) float          g_fd[Nn * INd];   // feat_dst (N,128)
__device__ __align__(16) __nv_bfloat162 g_ybf[Nn * 256];  // y in bf16 (51 MB -> L2-resident)
__device__               int            g_cnt[2][Nn];     // in-degree histogram
__device__               int            g_off[2][Nn];     // CSR slot base
__device__               int            g_cur[2][Nn];     // fill cursors
__device__               int            g_srcs[2][Ee];    // src ids, grouped by dst
__device__               int            g_total[2];       // slot allocator
__device__               int            g_flag_fmt;       // 0=int32, 1=uint8, 2=float32

// ---------------- init: flag detect (block 0) + zero histograms/totals ----------------
__global__ void k_init(const unsigned* __restrict__ p) {
    if (blockIdx.x == 0) {
        __shared__ int s_word_not01, s_byte_not01;
        if (threadIdx.x == 0) { s_word_not01 = 0; s_byte_not01 = 0; g_total[0] = 0; g_total[1] = 0; }
        __syncthreads();
        const int nwords = Nn / 4;
        int w_bad = 0, b_bad = 0;
        for (int i = threadIdx.x; i < nwords; i += blockDim.x) {
            unsigned w = p[i];
            if (w > 1u) w_bad = 1;
            unsigned b0 = w & 0xFFu, b1 = (w >> 8) & 0xFFu, b2 = (w >> 16) & 0xFFu, b3 = (w >> 24) & 0xFFu;
            if (b0 > 1u || b1 > 1u || b2 > 1u || b3 > 1u) b_bad = 1;
        }
        if (w_bad) atomicOr(&s_word_not01, 1);
        if (b_bad) atomicOr(&s_byte_not01, 1);
        __syncthreads();
        if (threadIdx.x == 0) {
            int fmt;
            if (!s_word_not01) fmt = 0;
            else if (!s_byte_not01) fmt = 1;
            else fmt = 2;
            g_flag_fmt = fmt;
        }
    } else {
        int tid = (blockIdx.x - 1) * blockDim.x + threadIdx.x;
        int stride = (gridDim.x - 1) * blockDim.x;
        int* cnt = (int*)g_cnt;
        for (int i = tid; i < 2 * Nn; i += stride) cnt[i] = 0;
    }
}

// ---------------- y -> bf16 conversion (one pass, streaming) ----------------
__global__ void k_ycvt(const float2* __restrict__ y2) {
    const int total = Nn * 256;
    int i = blockIdx.x * blockDim.x + threadIdx.x;
    const int stride = gridDim.x * blockDim.x;
    for (; i < total; i += stride)
        g_ybf[i] = __float22bfloat162_rn(__ldcs(y2 + i));
}

// ---------------- projection: fs = x W_src^T + b_src ; fd likewise ----------------
#define BR 16
__global__ void k_proj(const float* __restrict__ x,
                       const float* __restrict__ Ws, const float* __restrict__ bs,
                       const float* __restrict__ Wd, const float* __restrict__ bd) {
    __shared__ float xs[BR][INd];
    const int row0 = blockIdx.x * BR;
    for (int i = threadIdx.x; i < BR * INd; i += blockDim.x) {
        int r = i / INd, c = i % INd;
        xs[r][c] = x[(row0 + r) * INd + c];
    }
    __syncthreads();
    const int col = threadIdx.x;
    float accS[BR], accD[BR];
#pragma unroll
    for (int r = 0; r < BR; r++) { accS[r] = 0.f; accD[r] = 0.f; }
    const float* wsr = Ws + col * INd;
    const float* wdr = Wd + col * INd;
    for (int k = 0; k < INd; k++) {
        float ws = __ldg(wsr + k);
        float wd = __ldg(wdr + k);
#pragma unroll
        for (int r = 0; r < BR; r++) {
            float xv = xs[r][k];
            accS[r] += xv * ws;
            accD[r] += xv * wd;
        }
    }
    float bsv = bs[col], bdv = bd[col];
#pragma unroll
    for (int r = 0; r < BR; r++) {
        g_fs[(row0 + r) * INd + col] = accS[r] + bsv;
        g_fd[(row0 + r) * INd + col] = accD[r] + bdv;
    }
}

// ---------------- CSR build: histogram -> block-aggregated alloc -> fill ----------------
__global__ void k_hist(const int* __restrict__ dst_p, const int* __restrict__ dst_s, int et) {
    const int g = blockIdx.x >= et;
    const int e = (blockIdx.x - g * et) * blockDim.x + threadIdx.x;
    if (e < Ee) atomicAdd(&g_cnt[g][(g ? dst_s : dst_p)[e]], 1);
}

// 256 threads/block, one node each; in-block exclusive scan + ONE atomic per block.
__global__ void k_alloc(int nbg) {
    const int g = blockIdx.x >= nbg;
    const int b = blockIdx.x - g * nbg;
    const int n = b * 256 + threadIdx.x;
    const int lane = threadIdx.x & 31;
    const int w = threadIdx.x >> 5;

    __shared__ int wsum[8];
    __shared__ int s_base;

    const int c = (n < Nn) ? g_cnt[g][n] : 0;
    int v = c;   // inclusive scan within warp
#pragma unroll
    for (int o = 1; o < 32; o <<= 1) {
        int u = __shfl_up_sync(0xFFFFFFFFu, v, o);
        if (lane >= o) v += u;
    }
    if (lane == 31) wsum[w] = v;
    __syncthreads();
    if (threadIdx.x == 0) {
        int run = 0;
#pragma unroll
        for (int i = 0; i < 8; i++) { int t = wsum[i]; wsum[i] = run; run += t; }
        s_base = (run > 0) ? atomicAdd(&g_total[g], run) : 0;
    }
    __syncthreads();
    if (n < Nn) {
        const int excl = (v - c) + wsum[w] + s_base;
        g_off[g][n] = excl;
        g_cur[g][n] = excl;
    }
}

__global__ void k_fill(const int* __restrict__ src_p, const int* __restrict__ dst_p,
                       const int* __restrict__ src_s, const int* __restrict__ dst_s, int et) {
    const int g = blockIdx.x >= et;
    const int e = (blockIdx.x - g * et) * blockDim.x + threadIdx.x;
    if (e >= Ee) return;
    const int d = (g ? dst_s : dst_p)[e];
    const int s = (g ? src_s : src_p)[e];
    int pos = atomicAdd(&g_cur[g][d], 1);
    g_srcs[g][pos] = s;
}

// ---------------- fused gather: softmax + aggregation + epilogues ----------------
__global__ void __launch_bounds__(256) k_gather(
        const float* __restrict__ x, const float* __restrict__ y,
        const float* __restrict__ attn, const void* __restrict__ flag,
        float* __restrict__ out) {
    const int warp = threadIdx.x >> 5;
    const int lane = threadIdx.x & 31;
    const int n = blockIdx.x * (blockDim.x >> 5) + warp;
    if (n >= Nn) return;

    __shared__ float4 s_ex[8][MAXD];    // 16 KB: per-edge exp(logit) by head
    __shared__ int    s_src[8][MAXD];   // 4 KB: per-edge src id

    const float4* __restrict__ fs4p = (const float4*)g_fs;
    const uint2*  __restrict__ yb2  = (const uint2*)g_ybf;   // 8 B = 4 bf16 per lane-chunk

    const float4 fd4 = __ldg(((const float4*)g_fd) + n * 32 + lane);   // once per node
    const float4 at  = __ldg(((const float4*)attn) + lane);

    float4 acc = __ldg(((const float4*)x) + n * 32 + lane);
    acc.x *= 2.f; acc.y *= 2.f; acc.z *= 2.f; acc.w *= 2.f;
    float4 yh[4];
#pragma unroll
    for (int i = 0; i < 4; i++) yh[i] = make_float4(0.f, 0.f, 0.f, 0.f);

#pragma unroll
    for (int g = 0; g < 2; g++) {
        const int beg = g_off[g][n];
        const int end = beg + g_cnt[g][n];
        const int* __restrict__ ps = g_srcs[g];

        // ---- pass 1: logits -> exp; accumulate fs*ex AND the denominator in registers
        float4 accp = make_float4(0.f, 0.f, 0.f, 0.f);
        float dsum = 0.f;   // denominator for head (lane>>3)
        for (int k = beg; k < end; k++) {
            const int idx = k - beg;
            const int s = __ldg(ps + k);
            const float4 f = __ldg(fs4p + s * 32 + lane);
            float v, p;
            v = f.x + fd4.x; v = v > 0.f ? v : SLOPE * v; p  = v * at.x;
            v = f.y + fd4.y; v = v > 0.f ? v : SLOPE * v; p += v * at.y;
            v = f.z + fd4.z; v = v > 0.f ? v : SLOPE * v; p += v * at.z;
            v = f.w + fd4.w; v = v > 0.f ? v : SLOPE * v; p += v * at.w;
            p += __shfl_xor_sync(0xFFFFFFFFu, p, 4);
            p += __shfl_xor_sync(0xFFFFFFFFu, p, 2);
            p += __shfl_xor_sync(0xFFFFFFFFu, p, 1);
            const float ex = expf(p);      // this lane's head value (uniform per 8-lane group)
            dsum += ex;
            accp.x += f.x * ex; accp.y += f.y * ex;
            accp.z += f.z * ex; accp.w += f.w * ex;
            const float e0 = __shfl_sync(0xFFFFFFFFu, ex, 0);
            const float e1 = __shfl_sync(0xFFFFFFFFu, ex, 8);
            const float e2 = __shfl_sync(0xFFFFFFFFu, ex, 16);
            const float e3 = __shfl_sync(0xFFFFFFFFu, ex, 24);
            if (idx < MAXD && lane == 0) {
                s_src[warp][idx] = s;
                s_ex[warp][idx] = make_float4(e0, e1, e2, e3);
            }
        }
        __syncwarp();
        const float d0 = __shfl_sync(0xFFFFFFFFu, dsum, 0);
        const float d1 = __shfl_sync(0xFFFFFFFFu, dsum, 8);
        const float d2 = __shfl_sync(0xFFFFFFFFu, dsum, 16);
        const float d3 = __shfl_sync(0xFFFFFFFFu, dsum, 24);
        float4 rs;
        rs.x = d0 > 0.f ? 1.f / d0 : 0.f;
        rs.y = d1 > 0.f ? 1.f / d1 : 0.f;
        rs.z = d2 > 0.f ? 1.f / d2 : 0.f;
        rs.w = d3 > 0.f ? 1.f / d3 : 0.f;
        const float rl = (lane < 8) ? rs.x : (lane < 16) ? rs.y : (lane < 24) ? rs.z : rs.w;
        acc.x += accp.x * rl; acc.y += accp.y * rl;
        acc.z += accp.z * rl; acc.w += accp.w * rl;

        // ---- pass 2: y gathers (bf16, L2-resident)
        for (int k = beg; k < end; k++) {
            const int idx = k - beg;
            int s; float4 e4;
            if (idx < MAXD) {
                s = s_src[warp][idx];
                e4 = s_ex[warp][idx];
            } else {            // never expected; correctness fallback
                s = __ldg(ps + k);
                const float4 f = __ldg(fs4p + s * 32 + lane);
                float v, p;
                v = f.x + fd4.x; v = v > 0.f ? v : SLOPE * v; p  = v * at.x;
                v = f.y + fd4.y; v = v > 0.f ? v : SLOPE * v; p += v * at.y;
                v = f.z + fd4.z; v = v > 0.f ? v : SLOPE * v; p += v * at.z;
                v = f.w + fd4.w; v = v > 0.f ? v : SLOPE * v; p += v * at.w;
                p += __shfl_xor_sync(0xFFFFFFFFu, p, 4);
                p += __shfl_xor_sync(0xFFFFFFFFu, p, 2);
                p += __shfl_xor_sync(0xFFFFFFFFu, p, 1);
                const float ex = expf(p);
                e4.x = __shfl_sync(0xFFFFFFFFu, ex, 0);
                e4.y = __shfl_sync(0xFFFFFFFFu, ex, 8);
                e4.z = __shfl_sync(0xFFFFFFFFu, ex, 16);
                e4.w = __shfl_sync(0xFFFFFFFFu, ex, 24);
            }
            const float am = 0.25f * (e4.x * rs.x + e4.y * rs.y + e4.z * rs.z + e4.w * rs.w);
            const uint2* py = yb2 + (size_t)s * 128;
#pragma unroll
            for (int i = 0; i < 4; i++) {
                const uint2 u = __ldg(py + i * 32 + lane);
                const float2 f0 = __bfloat1622float2(*(const __nv_bfloat162*)&u.x);
                const float2 f1 = __bfloat1622float2(*(const __nv_bfloat162*)&u.y);
                yh[i].x += f0.x * am; yh[i].y += f0.y * am;
                yh[i].z += f1.x * am; yh[i].w += f1.y * am;
            }
        }
        __syncwarp();
    }

    // ---- epilogue h: mean over heads + elu; heads of float f live in lanes {f/4, +8, +16, +24}
#pragma unroll
    for (int o = 8; o <= 16; o <<= 1) {
        acc.x += __shfl_xor_sync(0xFFFFFFFFu, acc.x, o);
        acc.y += __shfl_xor_sync(0xFFFFFFFFu, acc.y, o);
        acc.z += __shfl_xor_sync(0xFFFFFFFFu, acc.z, o);
        acc.w += __shfl_xor_sync(0xFFFFFFFFu, acc.w, o);
    }
    if (lane < 8) {
        float4 r;
        r.x = acc.x * 0.25f; r.y = acc.y * 0.25f; r.z = acc.z * 0.25f; r.w = acc.w * 0.25f;
        r.x = r.x > 0.f ? r.x : expm1f(r.x);
        r.y = r.y > 0.f ? r.y : expm1f(r.y);
        r.z = r.z > 0.f ? r.z : expm1f(r.z);
        r.w = r.w > 0.f ? r.w : expm1f(r.w);
        ((float4*)out)[n * 8 + lane] = r;
    }

    // ---- epilogue y: L2 normalize or passthrough per flag (passthrough stays exact fp32)
    float ssq = 0.f;
#pragma unroll
    for (int i = 0; i < 4; i++)
        ssq += yh[i].x * yh[i].x + yh[i].y * yh[i].y + yh[i].z * yh[i].z + yh[i].w * yh[i].w;
#pragma unroll
    for (int o = 16; o; o >>= 1) ssq += __shfl_xor_sync(0xFFFFFFFFu, ssq, o);
    const float inv = 1.f / fmaxf(sqrtf(ssq), 1e-12f);

    bool f;
    const int fmt = g_flag_fmt;
    if (fmt == 0)      f = ((const int*)flag)[n] != 0;
    else if (fmt == 1) f = ((const unsigned char*)flag)[n] != 0;
    else               f = ((const float*)flag)[n] != 0.f;

    float4* po = (float4*)(out + (size_t)Nn * Ff) + (size_t)n * 128;
    if (f) {
        const float4* py = ((const float4*)y) + (size_t)n * 128;
#pragma unroll
        for (int i = 0; i < 4; i++) po[i * 32 + lane] = __ldg(py + i * 32 + lane);
    } else {
#pragma unroll
        for (int i = 0; i < 4; i++) {
            float4 w = yh[i];
            w.x *= inv; w.y *= inv; w.z *= inv; w.w *= inv;
            po[i * 32 + lane] = w;
        }
    }
}

// ---------------- launch ----------------
extern "C" void kernel_launch(void* const* d_in, const int* in_sizes, int n_in,
                              void* d_out, int out_size) {
    const float* x     = (const float*)d_in[0];
    const float* y     = (const float*)d_in[1];
    const float* Ws    = (const float*)d_in[2];
    const float* bs    = (const float*)d_in[3];
    const float* Wd    = (const float*)d_in[4];
    const float* bd    = (const float*)d_in[5];
    const float* attn  = (const float*)d_in[6];
    const int*   src_p = (const int*)d_in[7];
    const int*   dst_p = (const int*)d_in[8];
    const int*   src_s = (const int*)d_in[9];
    const int*   dst_s = (const int*)d_in[10];
    const void*  dflag = d_in[11];
    float* out = (float*)d_out;

    const int et = (Ee + 255) / 256;     // thread-per-edge blocks (per graph)
    const int nbg = (Nn + 255) / 256;    // alloc blocks (per graph)

    k_init<<<129, 256>>>((const unsigned*)dflag);
    k_ycvt<<<2048, 256>>>((const float2*)y);
    k_proj<<<Nn / BR, 128>>>(x, Ws, bs, Wd, bd);

    k_hist<<<2 * et, 256>>>(dst_p, dst_s, et);
    k_alloc<<<2 * nbg, 256>>>(nbg);
    k_fill<<<2 * et, 256>>>(src_p, dst_p, src_s, dst_s, et);

    k_gather<<<(Nn + 7) / 8, 256>>>(x, y, attn, dflag, out);
}

// round 15
// speedup vs baseline: 1.0578x; 1.0052x over previous
#include <cuda_runtime.h>
#include <cuda_bf16.h>

#define Nn 50000
#define INd 128
#define Hh 4
#define Ff 32
#define Ee 500000
#define Ll 512
#define SLOPE 0.2f
#define MAXD 128   // per-warp smem edge stash; P(deg>=128 | Poisson(10)) ~ 1e-80

// ---------------- device scratch (static, allocation-free) ----------------
__device__ __align__(16) float          g_fs[Nn * INd];   // feat_src (N,128)
__device__ __align__(16) float          g_fd[Nn * INd];   // feat_dst (N,128)
__device__ __align__(16) __nv_bfloat162 g_ybf[Nn * 256];  // y in bf16 (51 MB -> L2-resident)
__device__               int            g_cnt[2][Nn];     // in-degree histogram
__device__               int            g_off[2][Nn];     // CSR slot base
__device__               int            g_cur[2][Nn];     // fill cursors
__device__               int            g_srcs[2][Ee];    // src ids, grouped by dst
__device__               int            g_total[2];       // slot allocator
__device__               int            g_flag_fmt;       // 0=int32, 1=uint8, 2=float32

// ---------------- init: flag detect (block 0) + zero hist + y->bf16 convert ----------------
__global__ void k_init(const unsigned* __restrict__ p, const float2* __restrict__ y2) {
    if (blockIdx.x == 0) {
        __shared__ int s_word_not01, s_byte_not01;
        if (threadIdx.x == 0) { s_word_not01 = 0; s_byte_not01 = 0; g_total[0] = 0; g_total[1] = 0; }
        __syncthreads();
        const int nwords = Nn / 4;
        int w_bad = 0, b_bad = 0;
        for (int i = threadIdx.x; i < nwords; i += blockDim.x) {
            unsigned w = p[i];
            if (w > 1u) w_bad = 1;
            unsigned b0 = w & 0xFFu, b1 = (w >> 8) & 0xFFu, b2 = (w >> 16) & 0xFFu, b3 = (w >> 24) & 0xFFu;
            if (b0 > 1u || b1 > 1u || b2 > 1u || b3 > 1u) b_bad = 1;
        }
        if (w_bad) atomicOr(&s_word_not01, 1);
        if (b_bad) atomicOr(&s_byte_not01, 1);
        __syncthreads();
        if (threadIdx.x == 0) {
            int fmt;
            if (!s_word_not01) fmt = 0;
            else if (!s_byte_not01) fmt = 1;
            else fmt = 2;
            g_flag_fmt = fmt;
        }
    } else if (blockIdx.x <= 128) {
        int tid = (blockIdx.x - 1) * blockDim.x + threadIdx.x;
        int stride = 128 * blockDim.x;
        int* cnt = (int*)g_cnt;
        for (int i = tid; i < 2 * Nn; i += stride) cnt[i] = 0;
    } else {
        const int total = Nn * 256;
        int i = (blockIdx.x - 129) * blockDim.x + threadIdx.x;
        const int stride = (gridDim.x - 129) * blockDim.x;
        for (; i < total; i += stride)
            g_ybf[i] = __float22bfloat162_rn(__ldcs(y2 + i));
    }
}

// ---------------- projection: fs = x W_src^T + b_src ; fd likewise ----------------
#define BR 16
__global__ void k_proj(const float* __restrict__ x,
                       const float* __restrict__ Ws, const float* __restrict__ bs,
                       const float* __restrict__ Wd, const float* __restrict__ bd) {
    __shared__ float xs[BR][INd];
    const int row0 = blockIdx.x * BR;
    for (int i = threadIdx.x; i < BR * INd; i += blockDim.x) {
        int r = i / INd, c = i % INd;
        xs[r][c] = x[(row0 + r) * INd + c];
    }
    __syncthreads();
    const int col = threadIdx.x;
    float accS[BR], accD[BR];
#pragma unroll
    for (int r = 0; r < BR; r++) { accS[r] = 0.f; accD[r] = 0.f; }
    const float* wsr = Ws + col * INd;
    const float* wdr = Wd + col * INd;
    for (int k = 0; k < INd; k++) {
        float ws = __ldg(wsr + k);
        float wd = __ldg(wdr + k);
#pragma unroll
        for (int r = 0; r < BR; r++) {
            float xv = xs[r][k];
            accS[r] += xv * ws;
            accD[r] += xv * wd;
        }
    }
    float bsv = bs[col], bdv = bd[col];
#pragma unroll
    for (int r = 0; r < BR; r++) {
        g_fs[(row0 + r) * INd + col] = accS[r] + bsv;
        g_fd[(row0 + r) * INd + col] = accD[r] + bdv;
    }
}

// ---------------- CSR build: histogram -> block-aggregated alloc -> fill ----------------
__global__ void k_hist(const int* __restrict__ dst_p, const int* __restrict__ dst_s, int et) {
    const int g = blockIdx.x >= et;
    const int e = (blockIdx.x - g * et) * blockDim.x + threadIdx.x;
    if (e < Ee) atomicAdd(&g_cnt[g][(g ? dst_s : dst_p)[e]], 1);
}

__global__ void k_alloc(int nbg) {
    const int g = blockIdx.x >= nbg;
    const int b = blockIdx.x - g * nbg;
    const int n = b * 256 + threadIdx.x;
    const int lane = threadIdx.x & 31;
    const int w = threadIdx.x >> 5;

    __shared__ int wsum[8];
    __shared__ int s_base;

    const int c = (n < Nn) ? g_cnt[g][n] : 0;
    int v = c;
#pragma unroll
    for (int o = 1; o < 32; o <<= 1) {
        int u = __shfl_up_sync(0xFFFFFFFFu, v, o);
        if (lane >= o) v += u;
    }
    if (lane == 31) wsum[w] = v;
    __syncthreads();
    if (threadIdx.x == 0) {
        int run = 0;
#pragma unroll
        for (int i = 0; i < 8; i++) { int t = wsum[i]; wsum[i] = run; run += t; }
        s_base = (run > 0) ? atomicAdd(&g_total[g], run) : 0;
    }
    __syncthreads();
    if (n < Nn) {
        const int excl = (v - c) + wsum[w] + s_base;
        g_off[g][n] = excl;
        g_cur[g][n] = excl;
    }
}

__global__ void k_fill(const int* __restrict__ src_p, const int* __restrict__ dst_p,
                       const int* __restrict__ src_s, const int* __restrict__ dst_s, int et) {
    const int g = blockIdx.x >= et;
    const int e = (blockIdx.x - g * et) * blockDim.x + threadIdx.x;
    if (e >= Ee) return;
    const int d = (g ? dst_s : dst_p)[e];
    const int s = (g ? src_s : src_p)[e];
    int pos = atomicAdd(&g_cur[g][d], 1);
    g_srcs[g][pos] = s;
}

// ---------------- fused gather: pipelined softmax + aggregation + epilogues ----------------
__global__ void __launch_bounds__(256) k_gather(
        const float* __restrict__ x, const float* __restrict__ y,
        const float* __restrict__ attn, const void* __restrict__ flag,
        float* __restrict__ out) {
    const int warp = threadIdx.x >> 5;
    const int lane = threadIdx.x & 31;
    const int n = blockIdx.x * (blockDim.x >> 5) + warp;
    if (n >= Nn) return;

    __shared__ float4 s_ex[8][MAXD];    // 16 KB: per-edge exp(logit) by head
    __shared__ int    s_src[8][MAXD];   // 4 KB: per-edge src id

    const float4* __restrict__ fs4p = (const float4*)g_fs;
    const uint2*  __restrict__ yb2  = (const uint2*)g_ybf;

    const float4 fd4 = __ldg(((const float4*)g_fd) + n * 32 + lane);
    const float4 at  = __ldg(((const float4*)attn) + lane);

    float4 acc = __ldg(((const float4*)x) + n * 32 + lane);
    acc.x *= 2.f; acc.y *= 2.f; acc.z *= 2.f; acc.w *= 2.f;
    float4 yh[4];
#pragma unroll
    for (int i = 0; i < 4; i++) yh[i] = make_float4(0.f, 0.f, 0.f, 0.f);

#pragma unroll
    for (int g = 0; g < 2; g++) {
        const int beg = g_off[g][n];
        const int cnt = g_cnt[g][n];
        const int* __restrict__ ps = g_srcs[g] + beg;

        // ---- pass 1: software-pipelined (src ids 3 ahead, fs rows 2 ahead)
        float4 accp = make_float4(0.f, 0.f, 0.f, 0.f);
        float dsum = 0.f;
        int s0 = 0, s1 = 0, s2 = 0;
        float4 f0 = make_float4(0.f, 0.f, 0.f, 0.f), f1 = f0;
        if (cnt > 0) s0 = __ldg(ps + 0);
        if (cnt > 1) s1 = __ldg(ps + 1);
        if (cnt > 2) s2 = __ldg(ps + 2);
        if (cnt > 0) f0 = __ldg(fs4p + s0 * 32 + lane);
        if (cnt > 1) f1 = __ldg(fs4p + s1 * 32 + lane);
        for (int k = 0; k < cnt; k++) {
            const int s3 = (k + 3 < cnt) ? __ldg(ps + k + 3) : 0;
            const float4 f2 = (k + 2 < cnt) ? __ldg(fs4p + s2 * 32 + lane)
                                            : make_float4(0.f, 0.f, 0.f, 0.f);
            float v, p;
            v = f0.x + fd4.x; v = v > 0.f ? v : SLOPE * v; p  = v * at.x;
            v = f0.y + fd4.y; v = v > 0.f ? v : SLOPE * v; p += v * at.y;
            v = f0.z + fd4.z; v = v > 0.f ? v : SLOPE * v; p += v * at.z;
            v = f0.w + fd4.w; v = v > 0.f ? v : SLOPE * v; p += v * at.w;
            p += __shfl_xor_sync(0xFFFFFFFFu, p, 4);
            p += __shfl_xor_sync(0xFFFFFFFFu, p, 2);
            p += __shfl_xor_sync(0xFFFFFFFFu, p, 1);
            const float ex = expf(p);      // this lane's head value (uniform per 8-lane group)
            dsum += ex;
            accp.x += f0.x * ex; accp.y += f0.y * ex;
            accp.z += f0.z * ex; accp.w += f0.w * ex;
            const float e0 = __shfl_sync(0xFFFFFFFFu, ex, 0);
            const float e1 = __shfl_sync(0xFFFFFFFFu, ex, 8);
            const float e2 = __shfl_sync(0xFFFFFFFFu, ex, 16);
            const float e3 = __shfl_sync(0xFFFFFFFFu, ex, 24);
            if (k < MAXD && lane == 0) {
                s_src[warp][k] = s0;
                s_ex[warp][k] = make_float4(e0, e1, e2, e3);
            }
            s0 = s1; s1 = s2; s2 = s3;
            f0 = f1; f1 = f2;
        }
        __syncwarp();
        const float d0 = __shfl_sync(0xFFFFFFFFu, dsum, 0);
        const float d1 = __shfl_sync(0xFFFFFFFFu, dsum, 8);
        const float d2 = __shfl_sync(0xFFFFFFFFu, dsum, 16);
        const float d3 = __shfl_sync(0xFFFFFFFFu, dsum, 24);
        float4 rs;
        rs.x = d0 > 0.f ? 1.f / d0 : 0.f;
        rs.y = d1 > 0.f ? 1.f / d1 : 0.f;
        rs.z = d2 > 0.f ? 1.f / d2 : 0.f;
        rs.w = d3 > 0.f ? 1.f / d3 : 0.f;
        const float rl = (lane < 8) ? rs.x : (lane < 16) ? rs.y : (lane < 24) ? rs.z : rs.w;
        acc.x += accp.x * rl; acc.y += accp.y * rl;
        acc.z += accp.z * rl; acc.w += accp.w * rl;

        // ---- pass 2: y gathers (bf16, L2-resident), 2-edge unroll from smem stash
        const int m = cnt < MAXD ? cnt : MAXD;
        int k = 0;
        for (; k + 1 < m; k += 2) {
            const int sa = s_src[warp][k];
            const int sb = s_src[warp][k + 1];
            const float4 ea = s_ex[warp][k];
            const float4 eb = s_ex[warp][k + 1];
            const float ama = 0.25f * (ea.x * rs.x + ea.y * rs.y + ea.z * rs.z + ea.w * rs.w);
            const float amb = 0.25f * (eb.x * rs.x + eb.y * rs.y + eb.z * rs.z + eb.w * rs.w);
            const uint2* pya = yb2 + (size_t)sa * 128;
            const uint2* pyb = yb2 + (size_t)sb * 128;
            uint2 ua[4], ub[4];
#pragma unroll
            for (int i = 0; i < 4; i++) { ua[i] = __ldg(pya + i * 32 + lane); }
#pragma unroll
            for (int i = 0; i < 4; i++) { ub[i] = __ldg(pyb + i * 32 + lane); }
#pragma unroll
            for (int i = 0; i < 4; i++) {
                float2 a0 = __bfloat1622float2(*(const __nv_bfloat162*)&ua[i].x);
                float2 a1 = __bfloat1622float2(*(const __nv_bfloat162*)&ua[i].y);
                float2 b0 = __bfloat1622float2(*(const __nv_bfloat162*)&ub[i].x);
                float2 b1 = __bfloat1622float2(*(const __nv_bfloat162*)&ub[i].y);
                yh[i].x += a0.x * ama + b0.x * amb;
                yh[i].y += a0.y * ama + b0.y * amb;
                yh[i].z += a1.x * ama + b1.x * amb;
                yh[i].w += a1.y * ama + b1.y * amb;
            }
        }
        for (; k < m; k++) {
            const int sa = s_src[warp][k];
            const float4 ea = s_ex[warp][k];
            const float ama = 0.25f * (ea.x * rs.x + ea.y * rs.y + ea.z * rs.z + ea.w * rs.w);
            const uint2* pya = yb2 + (size_t)sa * 128;
#pragma unroll
            for (int i = 0; i < 4; i++) {
                const uint2 u = __ldg(pya + i * 32 + lane);
                float2 a0 = __bfloat1622float2(*(const __nv_bfloat162*)&u.x);
                float2 a1 = __bfloat1622float2(*(const __nv_bfloat162*)&u.y);
                yh[i].x += a0.x * ama; yh[i].y += a0.y * ama;
                yh[i].z += a1.x * ama; yh[i].w += a1.y * ama;
            }
        }
        // fallback for stash overflow (never expected): recompute ex from fs
        for (int kk = MAXD; kk < cnt; kk++) {
            const int s = __ldg(ps + kk);
            const float4 f = __ldg(fs4p + s * 32 + lane);
            float v, p;
            v = f.x + fd4.x; v = v > 0.f ? v : SLOPE * v; p  = v * at.x;
            v = f.y + fd4.y; v = v > 0.f ? v : SLOPE * v; p += v * at.y;
            v = f.z + fd4.z; v = v > 0.f ? v : SLOPE * v; p += v * at.z;
            v = f.w + fd4.w; v = v > 0.f ? v : SLOPE * v; p += v * at.w;
            p += __shfl_xor_sync(0xFFFFFFFFu, p, 4);
            p += __shfl_xor_sync(0xFFFFFFFFu, p, 2);
            p += __shfl_xor_sync(0xFFFFFFFFu, p, 1);
            const float ex = expf(p);
            float4 e4;
            e4.x = __shfl_sync(0xFFFFFFFFu, ex, 0);
            e4.y = __shfl_sync(0xFFFFFFFFu, ex, 8);
            e4.z = __shfl_sync(0xFFFFFFFFu, ex, 16);
            e4.w = __shfl_sync(0xFFFFFFFFu, ex, 24);
            const float am = 0.25f * (e4.x * rs.x + e4.y * rs.y + e4.z * rs.z + e4.w * rs.w);
            const uint2* py = yb2 + (size_t)s * 128;
#pragma unroll
            for (int i = 0; i < 4; i++) {
                const uint2 u = __ldg(py + i * 32 + lane);
                float2 a0 = __bfloat1622float2(*(const __nv_bfloat162*)&u.x);
                float2 a1 = __bfloat1622float2(*(const __nv_bfloat162*)&u.y);
                yh[i].x += a0.x * am; yh[i].y += a0.y * am;
                yh[i].z += a1.x * am; yh[i].w += a1.y * am;
            }
        }
        __syncwarp();
    }

    // ---- epilogue h: mean over heads + elu
#pragma unroll
    for (int o = 8; o <= 16; o <<= 1) {
        acc.x += __shfl_xor_sync(0xFFFFFFFFu, acc.x, o);
        acc.y += __shfl_xor_sync(0xFFFFFFFFu, acc.y, o);
        acc.z += __shfl_xor_sync(0xFFFFFFFFu, acc.z, o);
        acc.w += __shfl_xor_sync(0xFFFFFFFFu, acc.w, o);
    }
    if (lane < 8) {
        float4 r;
        r.x = acc.x * 0.25f; r.y = acc.y * 0.25f; r.z = acc.z * 0.25f; r.w = acc.w * 0.25f;
        r.x = r.x > 0.f ? r.x : expm1f(r.x);
        r.y = r.y > 0.f ? r.y : expm1f(r.y);
        r.z = r.z > 0.f ? r.z : expm1f(r.z);
        r.w = r.w > 0.f ? r.w : expm1f(r.w);
        ((float4*)out)[n * 8 + lane] = r;
    }

    // ---- epilogue y: L2 normalize or passthrough per flag (passthrough exact fp32)
    float ssq = 0.f;
#pragma unroll
    for (int i = 0; i < 4; i++)
        ssq += yh[i].x * yh[i].x + yh[i].y * yh[i].y + yh[i].z * yh[i].z + yh[i].w * yh[i].w;
#pragma unroll
    for (int o = 16; o; o >>= 1) ssq += __shfl_xor_sync(0xFFFFFFFFu, ssq, o);
    const float inv = 1.f / fmaxf(sqrtf(ssq), 1e-12f);

    bool f;
    const int fmt = g_flag_fmt;
    if (fmt == 0)      f = ((const int*)flag)[n] != 0;
    else if (fmt == 1) f = ((const unsigned char*)flag)[n] != 0;
    else               f = ((const float*)flag)[n] != 0.f;

    float4* po = (float4*)(out + (size_t)Nn * Ff) + (size_t)n * 128;
    if (f) {
        const float4* py = ((const float4*)y) + (size_t)n * 128;
#pragma unroll
        for (int i = 0; i < 4; i++) po[i * 32 + lane] = __ldg(py + i * 32 + lane);
    } else {
#pragma unroll
        for (int i = 0; i < 4; i++) {
            float4 w = yh[i];
            w.x *= inv; w.y *= inv; w.z *= inv; w.w *= inv;
            po[i * 32 + lane] = w;
        }
    }
}

// ---------------- launch ----------------
extern "C" void kernel_launch(void* const* d_in, const int* in_sizes, int n_in,
                              void* d_out, int out_size) {
    const float* x     = (const float*)d_in[0];
    const float* y     = (const float*)d_in[1];
    const float* Ws    = (const float*)d_in[2];
    const float* bs    = (const float*)d_in[3];
    const float* Wd    = (const float*)d_in[4];
    const float* bd    = (const float*)d_in[5];
    const float* attn  = (const float*)d_in[6];
    const int*   src_p = (const int*)d_in[7];
    const int*   dst_p = (const int*)d_in[8];
    const int*   src_s = (const int*)d_in[9];
    const int*   dst_s = (const int*)d_in[10];
    const void*  dflag = d_in[11];
    float* out = (float*)d_out;

    const int et = (Ee + 255) / 256;
    const int nbg = (Nn + 255) / 256;

    k_init<<<129 + 1024, 256>>>((const unsigned*)dflag, (const float2*)y);
    k_proj<<<Nn / BR, 128>>>(x, Ws, bs, Wd, bd);

    k_hist<<<2 * et, 256>>>(dst_p, dst_s, et);
    k_alloc<<<2 * nbg, 256>>>(nbg);
    k_fill<<<2 * et, 256>>>(src_p, dst_p, src_s, dst_s, et);

    k_gather<<<(Nn + 7) / 8, 256>>>(x, y, attn, dflag, out);
}

// round 16
// speedup vs baseline: 1.1567x; 1.0935x over previous
#include <cuda_runtime.h>
#include <cuda_bf16.h>

#define Nn 50000
#define INd 128
#define Hh 4
#define Ff 32
#define Ee 500000
#define Ll 512
#define SLOPE 0.2f
#define MAXD 128   // per-warp smem edge stash; P(deg>=128 | Poisson(10)) ~ 1e-80

// ---------------- device scratch (static, allocation-free) ----------------
__device__ __align__(16) float          g_fs[Nn * INd];   // feat_src (N,128)
__device__ __align__(16) float          g_fd[Nn * INd];   // feat_dst (N,128)
__device__ __align__(16) __nv_bfloat162 g_ybf[Nn * 256];  // y in bf16 (51 MB -> L2-resident)
__device__ __align__(16) float          g_am[2][Ee];      // final head-mean attention per edge
__device__               int            g_cnt[2][Nn];     // in-degree histogram
__device__               int            g_off[2][Nn];     // CSR slot base
__device__               int            g_cur[2][Nn];     // fill cursors
__device__               int            g_srcs[2][Ee];    // src ids, grouped by dst
__device__               int            g_total[2];       // slot allocator
__device__               int            g_flag_fmt;       // 0=int32, 1=uint8, 2=float32

// ---------------- init: flag detect (block 0) + zero hist + y->bf16 convert ----------------
__global__ void k_init(const unsigned* __restrict__ p, const float2* __restrict__ y2) {
    if (blockIdx.x == 0) {
        __shared__ int s_word_not01, s_byte_not01;
        if (threadIdx.x == 0) { s_word_not01 = 0; s_byte_not01 = 0; g_total[0] = 0; g_total[1] = 0; }
        __syncthreads();
        const int nwords = Nn / 4;
        int w_bad = 0, b_bad = 0;
        for (int i = threadIdx.x; i < nwords; i += blockDim.x) {
            unsigned w = p[i];
            if (w > 1u) w_bad = 1;
            unsigned b0 = w & 0xFFu, b1 = (w >> 8) & 0xFFu, b2 = (w >> 16) & 0xFFu, b3 = (w >> 24) & 0xFFu;
            if (b0 > 1u || b1 > 1u || b2 > 1u || b3 > 1u) b_bad = 1;
        }
        if (w_bad) atomicOr(&s_word_not01, 1);
        if (b_bad) atomicOr(&s_byte_not01, 1);
        __syncthreads();
        if (threadIdx.x == 0) {
            int fmt;
            if (!s_word_not01) fmt = 0;
            else if (!s_byte_not01) fmt = 1;
            else fmt = 2;
            g_flag_fmt = fmt;
        }
    } else if (blockIdx.x <= 128) {
        int tid = (blockIdx.x - 1) * blockDim.x + threadIdx.x;
        int stride = 128 * blockDim.x;
        int* cnt = (int*)g_cnt;
        for (int i = tid; i < 2 * Nn; i += stride) cnt[i] = 0;
    } else {
        const int total = Nn * 256;
        int i = (blockIdx.x - 129) * blockDim.x + threadIdx.x;
        const int stride = (gridDim.x - 129) * blockDim.x;
        for (; i < total; i += stride)
            g_ybf[i] = __float22bfloat162_rn(__ldcs(y2 + i));
    }
}

// ---------------- projection: fs = x W_src^T + b_src ; fd likewise ----------------
#define BR 16
__global__ void k_proj(const float* __restrict__ x,
                       const float* __restrict__ Ws, const float* __restrict__ bs,
                       const float* __restrict__ Wd, const float* __restrict__ bd) {
    __shared__ float xs[BR][INd];
    const int row0 = blockIdx.x * BR;
    for (int i = threadIdx.x; i < BR * INd; i += blockDim.x) {
        int r = i / INd, c = i % INd;
        xs[r][c] = x[(row0 + r) * INd + c];
    }
    __syncthreads();
    const int col = threadIdx.x;
    float accS[BR], accD[BR];
#pragma unroll
    for (int r = 0; r < BR; r++) { accS[r] = 0.f; accD[r] = 0.f; }
    const float* wsr = Ws + col * INd;
    const float* wdr = Wd + col * INd;
    for (int k = 0; k < INd; k++) {
        float ws = __ldg(wsr + k);
        float wd = __ldg(wdr + k);
#pragma unroll
        for (int r = 0; r < BR; r++) {
            float xv = xs[r][k];
            accS[r] += xv * ws;
            accD[r] += xv * wd;
        }
    }
    float bsv = bs[col], bdv = bd[col];
#pragma unroll
    for (int r = 0; r < BR; r++) {
        g_fs[(row0 + r) * INd + col] = accS[r] + bsv;
        g_fd[(row0 + r) * INd + col] = accD[r] + bdv;
    }
}

// ---------------- CSR build: histogram -> block-aggregated alloc -> fill ----------------
__global__ void k_hist(const int* __restrict__ dst_p, const int* __restrict__ dst_s, int et) {
    const int g = blockIdx.x >= et;
    const int e = (blockIdx.x - g * et) * blockDim.x + threadIdx.x;
    if (e < Ee) atomicAdd(&g_cnt[g][(g ? dst_s : dst_p)[e]], 1);
}

__global__ void k_alloc(int nbg) {
    const int g = blockIdx.x >= nbg;
    const int b = blockIdx.x - g * nbg;
    const int n = b * 256 + threadIdx.x;
    const int lane = threadIdx.x & 31;
    const int w = threadIdx.x >> 5;

    __shared__ int wsum[8];
    __shared__ int s_base;

    const int c = (n < Nn) ? g_cnt[g][n] : 0;
    int v = c;
#pragma unroll
    for (int o = 1; o < 32; o <<= 1) {
        int u = __shfl_up_sync(0xFFFFFFFFu, v, o);
        if (lane >= o) v += u;
    }
    if (lane == 31) wsum[w] = v;
    __syncthreads();
    if (threadIdx.x == 0) {
        int run = 0;
#pragma unroll
        for (int i = 0; i < 8; i++) { int t = wsum[i]; wsum[i] = run; run += t; }
        s_base = (run > 0) ? atomicAdd(&g_total[g], run) : 0;
    }
    __syncthreads();
    if (n < Nn) {
        const int excl = (v - c) + wsum[w] + s_base;
        g_off[g][n] = excl;
        g_cur[g][n] = excl;
    }
}

__global__ void k_fill(const int* __restrict__ src_p, const int* __restrict__ dst_p,
                       const int* __restrict__ src_s, const int* __restrict__ dst_s, int et) {
    const int g = blockIdx.x >= et;
    const int e = (blockIdx.x - g * et) * blockDim.x + threadIdx.x;
    if (e >= Ee) return;
    const int d = (g ? dst_s : dst_p)[e];
    const int s = (g ? src_s : src_p)[e];
    int pos = atomicAdd(&g_cur[g][d], 1);
    g_srcs[g][pos] = s;
}

// ---------------- feature kernel: softmax + fs aggregation + h epilogue + am export ----------------
__global__ void __launch_bounds__(256, 2) k_gfeat(
        const float* __restrict__ x, const float* __restrict__ attn,
        float* __restrict__ out) {
    const int warp = threadIdx.x >> 5;
    const int lane = threadIdx.x & 31;
    const int n = blockIdx.x * (blockDim.x >> 5) + warp;
    if (n >= Nn) return;

    __shared__ float4 s_ex[8][MAXD];    // 16 KB: per-edge exp(logit) by head

    const float4* __restrict__ fs4p = (const float4*)g_fs;
    const float4 fd4 = __ldg(((const float4*)g_fd) + n * 32 + lane);
    const float4 at  = __ldg(((const float4*)attn) + lane);

    float4 acc = __ldg(((const float4*)x) + n * 32 + lane);
    acc.x *= 2.f; acc.y *= 2.f; acc.z *= 2.f; acc.w *= 2.f;

#pragma unroll
    for (int g = 0; g < 2; g++) {
        const int beg = g_off[g][n];
        const int cnt = g_cnt[g][n];
        const int* __restrict__ ps = g_srcs[g] + beg;
        float* __restrict__ pam = g_am[g] + beg;

        float4 accp = make_float4(0.f, 0.f, 0.f, 0.f);
        float dsum = 0.f;   // denominator for head (lane>>3)
        for (int k = 0; k < cnt; k++) {
            const int s = __ldg(ps + k);
            const float4 f = __ldg(fs4p + s * 32 + lane);
            float v, p;
            v = f.x + fd4.x; v = v > 0.f ? v : SLOPE * v; p  = v * at.x;
            v = f.y + fd4.y; v = v > 0.f ? v : SLOPE * v; p += v * at.y;
            v = f.z + fd4.z; v = v > 0.f ? v : SLOPE * v; p += v * at.z;
            v = f.w + fd4.w; v = v > 0.f ? v : SLOPE * v; p += v * at.w;
            p += __shfl_xor_sync(0xFFFFFFFFu, p, 4);
            p += __shfl_xor_sync(0xFFFFFFFFu, p, 2);
            p += __shfl_xor_sync(0xFFFFFFFFu, p, 1);
            const float ex = expf(p);      // this lane's head value (uniform per 8-lane group)
            dsum += ex;
            accp.x += f.x * ex; accp.y += f.y * ex;
            accp.z += f.z * ex; accp.w += f.w * ex;
            const float e0 = __shfl_sync(0xFFFFFFFFu, ex, 0);
            const float e1 = __shfl_sync(0xFFFFFFFFu, ex, 8);
            const float e2 = __shfl_sync(0xFFFFFFFFu, ex, 16);
            const float e3 = __shfl_sync(0xFFFFFFFFu, ex, 24);
            if (k < MAXD && lane == 0)
                s_ex[warp][k] = make_float4(e0, e1, e2, e3);
        }
        __syncwarp();
        const float d0 = __shfl_sync(0xFFFFFFFFu, dsum, 0);
        const float d1 = __shfl_sync(0xFFFFFFFFu, dsum, 8);
        const float d2 = __shfl_sync(0xFFFFFFFFu, dsum, 16);
        const float d3 = __shfl_sync(0xFFFFFFFFu, dsum, 24);
        float4 rs;
        rs.x = d0 > 0.f ? 0.25f / d0 : 0.f;
        rs.y = d1 > 0.f ? 0.25f / d1 : 0.f;
        rs.z = d2 > 0.f ? 0.25f / d2 : 0.f;
        rs.w = d3 > 0.f ? 0.25f / d3 : 0.f;
        // fs-aggregation uses 1/d (not 0.25/d): scale rl by 4
        const float rl = 4.f * ((lane < 8) ? rs.x : (lane < 16) ? rs.y : (lane < 24) ? rs.z : rs.w);
        acc.x += accp.x * rl; acc.y += accp.y * rl;
        acc.z += accp.z * rl; acc.w += accp.w * rl;

        // export am per edge (coalesced across lanes)
        const int m = cnt < MAXD ? cnt : MAXD;
        for (int k = lane; k < m; k += 32) {
            const float4 e = s_ex[warp][k];
            pam[k] = e.x * rs.x + e.y * rs.y + e.z * rs.z + e.w * rs.w;
        }
        // overflow fallback (never expected): recompute warp-collectively
        for (int kk = MAXD; kk < cnt; kk++) {
            const int s = __ldg(ps + kk);
            const float4 f = __ldg(fs4p + s * 32 + lane);
            float v, p;
            v = f.x + fd4.x; v = v > 0.f ? v : SLOPE * v; p  = v * at.x;
            v = f.y + fd4.y; v = v > 0.f ? v : SLOPE * v; p += v * at.y;
            v = f.z + fd4.z; v = v > 0.f ? v : SLOPE * v; p += v * at.z;
            v = f.w + fd4.w; v = v > 0.f ? v : SLOPE * v; p += v * at.w;
            p += __shfl_xor_sync(0xFFFFFFFFu, p, 4);
            p += __shfl_xor_sync(0xFFFFFFFFu, p, 2);
            p += __shfl_xor_sync(0xFFFFFFFFu, p, 1);
            const float ex = expf(p);
            const float e0 = __shfl_sync(0xFFFFFFFFu, ex, 0);
            const float e1 = __shfl_sync(0xFFFFFFFFu, ex, 8);
            const float e2 = __shfl_sync(0xFFFFFFFFu, ex, 16);
            const float e3 = __shfl_sync(0xFFFFFFFFu, ex, 24);
            if (lane == 0)
                pam[kk] = e0 * rs.x + e1 * rs.y + e2 * rs.z + e3 * rs.w;
        }
        __syncwarp();
    }

    // ---- epilogue h: mean over heads + elu
#pragma unroll
    for (int o = 8; o <= 16; o <<= 1) {
        acc.x += __shfl_xor_sync(0xFFFFFFFFu, acc.x, o);
        acc.y += __shfl_xor_sync(0xFFFFFFFFu, acc.y, o);
        acc.z += __shfl_xor_sync(0xFFFFFFFFu, acc.z, o);
        acc.w += __shfl_xor_sync(0xFFFFFFFFu, acc.w, o);
    }
    if (lane < 8) {
        float4 r;
        r.x = acc.x * 0.25f; r.y = acc.y * 0.25f; r.z = acc.z * 0.25f; r.w = acc.w * 0.25f;
        r.x = r.x > 0.f ? r.x : expm1f(r.x);
        r.y = r.y > 0.f ? r.y : expm1f(r.y);
        r.z = r.z > 0.f ? r.z : expm1f(r.z);
        r.w = r.w > 0.f ? r.w : expm1f(r.w);
        ((float4*)out)[n * 8 + lane] = r;
    }
}

// ---------------- label kernel: lean y gather + normalize epilogue (high occupancy) ----------------
__global__ void __launch_bounds__(256, 4) k_glabel(
        const float* __restrict__ y, const void* __restrict__ flag,
        float* __restrict__ out) {
    const int warp = threadIdx.x >> 5;
    const int lane = threadIdx.x & 31;
    const int n = blockIdx.x * (blockDim.x >> 5) + warp;
    if (n >= Nn) return;
    (void)warp;

    const uint2* __restrict__ yb2 = (const uint2*)g_ybf;

    float4 yh[4];
#pragma unroll
    for (int i = 0; i < 4; i++) yh[i] = make_float4(0.f, 0.f, 0.f, 0.f);

#pragma unroll
    for (int g = 0; g < 2; g++) {
        const int beg = g_off[g][n];
        const int cnt = g_cnt[g][n];
        const int* __restrict__ ps = g_srcs[g] + beg;
        const float* __restrict__ pam = g_am[g] + beg;
        int k = 0;
        for (; k + 1 < cnt; k += 2) {
            const int sa = __ldg(ps + k);
            const int sb = __ldg(ps + k + 1);
            const float ama = __ldg(pam + k);
            const float amb = __ldg(pam + k + 1);
            const uint2* pya = yb2 + (size_t)sa * 128;
            const uint2* pyb = yb2 + (size_t)sb * 128;
            uint2 ua[4], ub[4];
#pragma unroll
            for (int i = 0; i < 4; i++) ua[i] = __ldg(pya + i * 32 + lane);
#pragma unroll
            for (int i = 0; i < 4; i++) ub[i] = __ldg(pyb + i * 32 + lane);
#pragma unroll
            for (int i = 0; i < 4; i++) {
                float2 a0 = __bfloat1622float2(*(const __nv_bfloat162*)&ua[i].x);
                float2 a1 = __bfloat1622float2(*(const __nv_bfloat162*)&ua[i].y);
                float2 b0 = __bfloat1622float2(*(const __nv_bfloat162*)&ub[i].x);
                float2 b1 = __bfloat1622float2(*(const __nv_bfloat162*)&ub[i].y);
                yh[i].x += a0.x * ama + b0.x * amb;
                yh[i].y += a0.y * ama + b0.y * amb;
                yh[i].z += a1.x * ama + b1.x * amb;
                yh[i].w += a1.y * ama + b1.y * amb;
            }
        }
        if (k < cnt) {
            const int sa = __ldg(ps + k);
            const float ama = __ldg(pam + k);
            const uint2* pya = yb2 + (size_t)sa * 128;
#pragma unroll
            for (int i = 0; i < 4; i++) {
                const uint2 u = __ldg(pya + i * 32 + lane);
                float2 a0 = __bfloat1622float2(*(const __nv_bfloat162*)&u.x);
                float2 a1 = __bfloat1622float2(*(const __nv_bfloat162*)&u.y);
                yh[i].x += a0.x * ama; yh[i].y += a0.y * ama;
                yh[i].z += a1.x * ama; yh[i].w += a1.y * ama;
            }
        }
    }

    // ---- epilogue y: L2 normalize or passthrough per flag (passthrough exact fp32)
    float ssq = 0.f;
#pragma unroll
    for (int i = 0; i < 4; i++)
        ssq += yh[i].x * yh[i].x + yh[i].y * yh[i].y + yh[i].z * yh[i].z + yh[i].w * yh[i].w;
#pragma unroll
    for (int o = 16; o; o >>= 1) ssq += __shfl_xor_sync(0xFFFFFFFFu, ssq, o);
    const float inv = 1.f / fmaxf(sqrtf(ssq), 1e-12f);

    bool f;
    const int fmt = g_flag_fmt;
    if (fmt == 0)      f = ((const int*)flag)[n] != 0;
    else if (fmt == 1) f = ((const unsigned char*)flag)[n] != 0;
    else               f = ((const float*)flag)[n] != 0.f;

    float4* po = (float4*)(out + (size_t)Nn * Ff) + (size_t)n * 128;
    if (f) {
        const float4* py = ((const float4*)y) + (size_t)n * 128;
#pragma unroll
        for (int i = 0; i < 4; i++) po[i * 32 + lane] = __ldg(py + i * 32 + lane);
    } else {
#pragma unroll
        for (int i = 0; i < 4; i++) {
            float4 w = yh[i];
            w.x *= inv; w.y *= inv; w.z *= inv; w.w *= inv;
            po[i * 32 + lane] = w;
        }
    }
}

// ---------------- launch ----------------
extern "C" void kernel_launch(void* const* d_in, const int* in_sizes, int n_in,
                              void* d_out, int out_size) {
    const float* x     = (const float*)d_in[0];
    const float* y     = (const float*)d_in[1];
    const float* Ws    = (const float*)d_in[2];
    const float* bs    = (const float*)d_in[3];
    const float* Wd    = (const float*)d_in[4];
    const float* bd    = (const float*)d_in[5];
    const float* attn  = (const float*)d_in[6];
    const int*   src_p = (const int*)d_in[7];
    const int*   dst_p = (const int*)d_in[8];
    const int*   src_s = (const int*)d_in[9];
    const int*   dst_s = (const int*)d_in[10];
    const void*  dflag = d_in[11];
    float* out = (float*)d_out;

    const int et = (Ee + 255) / 256;
    const int nbg = (Nn + 255) / 256;
    const int nw = (Nn + 7) / 8;

    k_init<<<129 + 1024, 256>>>((const unsigned*)dflag, (const float2*)y);
    k_proj<<<Nn / BR, 128>>>(x, Ws, bs, Wd, bd);

    k_hist<<<2 * et, 256>>>(dst_p, dst_s, et);
    k_alloc<<<2 * nbg, 256>>>(nbg);
    k_fill<<<2 * et, 256>>>(src_p, dst_p, src_s, dst_s, et);

    k_gfeat<<<nw, 256>>>(x, attn, out);
    k_glabel<<<nw, 256>>>(y, dflag, out);
}